// round 2
// baseline (speedup 1.0000x reference)
#include <cuda_runtime.h>
#include <cuda_bf16.h>
#include <math.h>

// Problem constants
#define NB    256   // BATCH
#define NH    256   // NHIDDEN == NHAGE
#define NI    16    // NINPUT
#define NIX   17    // NINPUT + 1
#define NT    501   // NSTEP
#define NG    768   // 3 * NHAGE
#define ND    69888 // NI*NH + NH*NH + NH
#define NO    8     // NOUT
#define FPIT  100

// -------------------- device scratch (statics: no runtime alloc) -----------
__device__ float g_hA[NH * NB];              // h, layout [j][b]
__device__ float g_hB[NH * NB];
__device__ float g_A [NB * NH * NH];         // A^T per batch: [b][k][h]
__device__ float g_Bm[NB * NI * NH];         // Bm per batch:  [b][i][h]
__device__ float g_C [NB * NH];              // [b][h]
__device__ float g_Bu[(size_t)NB * NT * NH]; // [b][t][h]

// -------------------- init ---------------------------------------------
__global__ void zero_h_kernel() {
    int i = blockIdx.x * 256 + threadIdx.x;
    g_hA[i] = 0.f;
}

// -------------------- GRU step ------------------------------------------
// grid (8, 16), 256 threads. blockIdx.x: 32-batch tile, blockIdx.y: 16-gate-row tile.
// Each thread: 2 batches x 1 gate-row x 3 strips (r,z,n).
__global__ void gru_step_kernel(const float* __restrict__ u,
                                const float* __restrict__ gWih,  // [768,17]
                                const float* __restrict__ gWhh,  // [768,256]
                                const float* __restrict__ gbih,
                                const float* __restrict__ gbhh,
                                const float* __restrict__ hsrc,  // [j][b]
                                float* __restrict__ hdst,
                                int t)
{
    const int tid = threadIdx.x;
    const int bt  = tid & 15;          // batch pair
    const int gl  = tid >> 4;          // 0..15 gate row within tile
    const int bTile = blockIdx.x * 32;
    const int g  = blockIdx.y * 16 + gl;   // 0..255 (hidden index)

    __shared__ float sW[3][16][32];
    __shared__ float sh[32][32];
    __shared__ float su[32][NIX];
    __shared__ float sWi[3][16][NIX];

    float aH[3][2], aI[3][2];
    #pragma unroll
    for (int s = 0; s < 3; s++) {
        float bi = gbih[s * NH + g];
        float bh = gbhh[s * NH + g];
        aI[s][0] = bi; aI[s][1] = bi;
        aH[s][0] = bh; aH[s][1] = bh;
    }

    // input tile (loaded once; first __syncthreads in K-loop covers ordering)
    for (int i = tid; i < 32 * NIX; i += 256) {
        int bb = i / NIX, ii = i % NIX;
        su[bb][ii] = u[(size_t)(bTile + bb) * (NT * NIX) + t * NIX + ii];
    }
    for (int i = tid; i < 3 * 16 * NIX; i += 256) {
        int s = i / (16 * NIX); int r = i % (16 * NIX);
        int gg = r / NIX, ii = r % NIX;
        sWi[s][gg][ii] = gWih[(s * NH + blockIdx.y * 16 + gg) * NIX + ii];
    }

    for (int k0 = 0; k0 < NH; k0 += 32) {
        __syncthreads();
        for (int i = tid; i < 3 * 16 * 32; i += 256) {
            int s = i >> 9; int r = i & 511;
            int gg = r >> 5, kk = r & 31;
            sW[s][gg][kk] = gWhh[(s * NH + blockIdx.y * 16 + gg) * NH + k0 + kk];
        }
        for (int i = tid; i < 1024; i += 256) {
            int kk = i >> 5, bb = i & 31;
            sh[kk][bb] = hsrc[(k0 + kk) * NB + bTile + bb];
        }
        __syncthreads();
        #pragma unroll 8
        for (int kk = 0; kk < 32; kk++) {
            float2 xv = *(const float2*)&sh[kk][bt * 2];
            #pragma unroll
            for (int s = 0; s < 3; s++) {
                float w = sW[s][gl][kk];
                aH[s][0] = fmaf(w, xv.x, aH[s][0]);
                aH[s][1] = fmaf(w, xv.y, aH[s][1]);
            }
        }
    }

    // input contribution (gi)
    #pragma unroll
    for (int ii = 0; ii < NIX; ii++) {
        float x0 = su[bt * 2 + 0][ii];
        float x1 = su[bt * 2 + 1][ii];
        #pragma unroll
        for (int s = 0; s < 3; s++) {
            float w = sWi[s][gl][ii];
            aI[s][0] = fmaf(w, x0, aI[s][0]);
            aI[s][1] = fmaf(w, x1, aI[s][1]);
        }
    }

    #pragma unroll
    for (int j = 0; j < 2; j++) {
        int b = bTile + bt * 2 + j;
        float r = 1.f / (1.f + expf(-(aI[0][j] + aH[0][j])));
        float z = 1.f / (1.f + expf(-(aI[1][j] + aH[1][j])));
        float n = tanhf(aI[2][j] + r * aH[2][j]);
        float hold = hsrc[g * NB + b];
        hdst[g * NB + b] = (1.f - z) * n + z * hold;
    }
}

// -------------------- hypernetwork GEMM ---------------------------------
// dparams[d][b] = sum_j Wage[d][j] * hT[j][b] + bage[d], routed into A/Bm/C.
// grid (1092, 4): 64-d x 64-b tiles, K=256. 256 threads, 4x4 accum per thread.
__global__ void hyper_kernel(const float* __restrict__ Wage,
                             const float* __restrict__ bage,
                             const float* __restrict__ Wih,   // [256,16]
                             const float* __restrict__ Whh,   // [256,256]
                             const float* __restrict__ bih,
                             const float* __restrict__ bhh,
                             const float* __restrict__ hT)    // [j][b]
{
    __shared__ float sWg[64][33];
    __shared__ float sh[32][64];

    const int d0 = blockIdx.x * 64;
    const int b0 = blockIdx.y * 64;
    const int bb0 = (threadIdx.x & 15) * 4;
    const int dd0 = (threadIdx.x >> 4) * 4;

    float acc[4][4] = {};

    for (int k0 = 0; k0 < NH; k0 += 32) {
        __syncthreads();
        for (int i = threadIdx.x; i < 2048; i += 256) {
            int dd = i >> 5, kk = i & 31;
            sWg[dd][kk] = Wage[(size_t)(d0 + dd) * NH + k0 + kk];
        }
        for (int i = threadIdx.x; i < 2048; i += 256) {
            int kk = i >> 6, bb = i & 63;
            sh[kk][bb] = hT[(k0 + kk) * NB + b0 + bb];
        }
        __syncthreads();
        #pragma unroll 8
        for (int kk = 0; kk < 32; kk++) {
            float4 hv = *(const float4*)&sh[kk][bb0];
            #pragma unroll
            for (int di = 0; di < 4; di++) {
                float wv = sWg[dd0 + di][kk];
                acc[di][0] = fmaf(wv, hv.x, acc[di][0]);
                acc[di][1] = fmaf(wv, hv.y, acc[di][1]);
                acc[di][2] = fmaf(wv, hv.z, acc[di][2]);
                acc[di][3] = fmaf(wv, hv.w, acc[di][3]);
            }
        }
    }

    #pragma unroll
    for (int di = 0; di < 4; di++) {
        int d = d0 + dd0 + di;
        float base = bage[d];
        #pragma unroll
        for (int bi = 0; bi < 4; bi++) {
            int b = b0 + bb0 + bi;
            float v = acc[di][bi] + base;
            if (d < NI * NH) {
                int hr = d >> 4, ii = d & 15;
                g_Bm[(size_t)b * (NI * NH) + ii * NH + hr] = v + Wih[d];
            } else if (d < NI * NH + NH * NH) {
                int dd = d - NI * NH;
                int hr = dd >> 8, kk = dd & 255;
                g_A[(size_t)b * (NH * NH) + kk * NH + hr] = v + Whh[dd];
            } else {
                int j = d - (NI * NH + NH * NH);
                g_C[b * NH + j] = v + bih[j] + bhh[j];
            }
        }
    }
}

// -------------------- Bu = einsum('bhi,bti->bth') -----------------------
// grid (256, 16), 256 threads. CTA = (batch, 32-timestep block). thread = h.
__global__ void bu_kernel(const float* __restrict__ u)
{
    __shared__ float sBm[NI][NH];
    __shared__ float su2[32][NI];

    const int b = blockIdx.x;
    const int tblk = blockIdx.y * 32;
    const int h = threadIdx.x;

    for (int i = threadIdx.x; i < NI * NH; i += 256) {
        sBm[i >> 8][i & 255] = g_Bm[(size_t)b * (NI * NH) + i];
    }
    for (int i = threadIdx.x; i < 32 * NI; i += 256) {
        int tt = i >> 4, ii = i & 15;
        int t = tblk + tt;
        su2[tt][ii] = (t < NT) ? u[(size_t)b * (NT * NIX) + t * NIX + ii] : 0.f;
    }
    __syncthreads();

    for (int tt = 0; tt < 32; tt++) {
        int t = tblk + tt;
        if (t >= NT) break;
        float acc = 0.f;
        #pragma unroll
        for (int ii = 0; ii < NI; ii++)
            acc = fmaf(sBm[ii][h], su2[tt][ii], acc);
        g_Bu[((size_t)b * NT + t) * NH + h] = acc;
    }
}

// -------------------- fixed point + Euler + output ----------------------
#define SMEM_K 128
#define REG_K  128

__device__ __forceinline__ float dotA(const float* __restrict__ sA,
                                      const float* __restrict__ Areg,
                                      const float* __restrict__ sx,
                                      int h)
{
    float acc = 0.f;
    const float4* sx4 = (const float4*)sx;
    #pragma unroll 4
    for (int k4 = 0; k4 < SMEM_K / 4; k4++) {
        float4 xv = sx4[k4];
        int kb = k4 * 4;
        acc = fmaf(sA[(kb + 0) * NH + h], xv.x, acc);
        acc = fmaf(sA[(kb + 1) * NH + h], xv.y, acc);
        acc = fmaf(sA[(kb + 2) * NH + h], xv.z, acc);
        acc = fmaf(sA[(kb + 3) * NH + h], xv.w, acc);
    }
    #pragma unroll
    for (int k4 = 0; k4 < REG_K / 4; k4++) {
        float4 xv = sx4[SMEM_K / 4 + k4];
        acc = fmaf(Areg[k4 * 4 + 0], xv.x, acc);
        acc = fmaf(Areg[k4 * 4 + 1], xv.y, acc);
        acc = fmaf(Areg[k4 * 4 + 2], xv.z, acc);
        acc = fmaf(Areg[k4 * 4 + 3], xv.w, acc);
    }
    return acc;
}

__global__ void __launch_bounds__(256, 1)
fpeuler_kernel(const float* __restrict__ tau,
               const float* __restrict__ Wout,  // [8,256]
               const float* __restrict__ bout,
               float* __restrict__ out)         // [b][t][8]
{
    extern __shared__ float sA[];                 // [SMEM_K][256]
    __shared__ __align__(16) float sx[NH];

    const int b = blockIdx.x;
    const int h = threadIdx.x;
    const float* __restrict__ Ab = g_A + (size_t)b * (NH * NH);

    for (int idx = h; idx < SMEM_K * NH; idx += 256)
        sA[idx] = Ab[idx];
    float Areg[REG_K];
    #pragma unroll
    for (int r = 0; r < REG_K; r++)
        Areg[r] = Ab[(SMEM_K + r) * NH + h];

    const float Cv  = g_C[b * NH + h];
    const float et  = expf(tau[h]);
    const float* __restrict__ BuB = g_Bu + (size_t)b * NT * NH + h;
    const float bu0 = BuB[0];

    const int w = h >> 5, l = h & 31;
    float wo[8];
    #pragma unroll
    for (int j = 0; j < 8; j++) wo[j] = Wout[w * NH + l * 8 + j];
    const float bo = bout[w];

    float myx = 0.f;
    sx[h] = 0.f;
    __syncthreads();

    // fixed point: x = et * tanh(A x + Bu0 + C), 100 iters
    for (int it = 0; it < FPIT; it++) {
        float acc = dotA(sA, Areg, sx, h);
        float xn = et * tanhf(acc + bu0 + Cv);
        __syncthreads();
        sx[h] = xn;
        myx = xn;
        __syncthreads();
    }

    // emit t = 0 (x0)
    {
        const float4* p = (const float4*)(sx + l * 8);
        float4 v0 = p[0], v1 = p[1];
        float a = wo[0] * v0.x;
        a = fmaf(wo[1], v0.y, a); a = fmaf(wo[2], v0.z, a); a = fmaf(wo[3], v0.w, a);
        a = fmaf(wo[4], v1.x, a); a = fmaf(wo[5], v1.y, a);
        a = fmaf(wo[6], v1.z, a); a = fmaf(wo[7], v1.w, a);
        #pragma unroll
        for (int off = 16; off; off >>= 1) a += __shfl_xor_sync(0xffffffffu, a, off);
        if (l == 0) out[((size_t)b * NT + 0) * NO + w] = a + bo;
    }

    // Euler: xn = x + tanh(A x + Bu[:,k] + C) - x/et, k = 0..499, traj[k+1] = xn
    float bu = bu0;
    for (int k = 0; k < NT - 1; k++) {
        float bu_nx = (k < NT - 2) ? BuB[(size_t)(k + 1) * NH] : 0.f;
        float acc = dotA(sA, Areg, sx, h);
        float xn = myx + tanhf(acc + bu + Cv) - myx / et;
        __syncthreads();
        sx[h] = xn;
        myx = xn;
        __syncthreads();

        const float4* p = (const float4*)(sx + l * 8);
        float4 v0 = p[0], v1 = p[1];
        float a = wo[0] * v0.x;
        a = fmaf(wo[1], v0.y, a); a = fmaf(wo[2], v0.z, a); a = fmaf(wo[3], v0.w, a);
        a = fmaf(wo[4], v1.x, a); a = fmaf(wo[5], v1.y, a);
        a = fmaf(wo[6], v1.z, a); a = fmaf(wo[7], v1.w, a);
        #pragma unroll
        for (int off = 16; off; off >>= 1) a += __shfl_xor_sync(0xffffffffu, a, off);
        if (l == 0) out[((size_t)b * NT + (k + 1)) * NO + w] = a + bo;

        bu = bu_nx;
    }
}

// -------------------- launch --------------------------------------------
extern "C" void kernel_launch(void* const* d_in, const int* in_sizes, int n_in,
                              void* d_out, int out_size)
{
    const float* u    = (const float*)d_in[0];
    const float* gWih = (const float*)d_in[1];
    const float* gWhh = (const float*)d_in[2];
    const float* gbih = (const float*)d_in[3];
    const float* gbhh = (const float*)d_in[4];
    const float* Wage = (const float*)d_in[5];
    const float* bage = (const float*)d_in[6];
    const float* Wih  = (const float*)d_in[7];
    const float* Whh  = (const float*)d_in[8];
    const float* bih  = (const float*)d_in[9];
    const float* bhh  = (const float*)d_in[10];
    const float* tau  = (const float*)d_in[11];
    const float* Wout = (const float*)d_in[12];
    const float* bout = (const float*)d_in[13];
    float* out = (float*)d_out;

    // h0 = 0
    zero_h_kernel<<<NH * NB / 256, 256>>>();

    // resolve ping-pong buffers via symbol addresses (host API, capture-safe)
    float *hA = nullptr, *hB = nullptr;
    cudaGetSymbolAddress((void**)&hA, g_hA);
    cudaGetSymbolAddress((void**)&hB, g_hB);

    // GRU scan: 501 sequential steps
    for (int t = 0; t < NT; t++) {
        const float* src = (t & 1) ? hB : hA;
        float*       dst = (t & 1) ? hA : hB;
        gru_step_kernel<<<dim3(8, 16), 256>>>(u, gWih, gWhh, gbih, gbhh, src, dst, t);
    }
    const float* hT = hB;  // t=500 (even) wrote into hB

    // hypernetwork: dparams -> A (transposed per batch), Bm, C
    hyper_kernel<<<dim3(ND / 64, NB / 64), 256>>>(Wage, bage, Wih, Whh, bih, bhh, hT);

    // Bu
    bu_kernel<<<dim3(NB, (NT + 31) / 32), 256>>>(u);

    // fixed point + Euler + output projection
    cudaFuncSetAttribute(fpeuler_kernel,
                         cudaFuncAttributeMaxDynamicSharedMemorySize,
                         SMEM_K * NH * (int)sizeof(float));
    fpeuler_kernel<<<NB, 256, SMEM_K * NH * sizeof(float)>>>(tau, Wout, bout, out);
}

// round 3
// speedup vs baseline: 1.2686x; 1.2686x over previous
#include <cuda_runtime.h>
#include <cuda_bf16.h>
#include <math.h>

// Problem constants
#define NB    256   // BATCH
#define NH    256   // NHIDDEN == NHAGE
#define NI    16    // NINPUT
#define NIX   17    // NINPUT + 1
#define NT    501   // NSTEP
#define ND    69888 // NI*NH + NH*NH + NH
#define NO    8     // NOUT
#define FPIT  100

// GRU persistent-cluster config
#define CLS   8     // CTAs per cluster
#define BG    16    // batches per cluster
#define HPC   32    // hidden indices per CTA
#define SHS   260   // padded h-row stride (floats)

// -------------------- device scratch --------------------------------------
__device__ float g_hx[2][NB][NH];            // h exchange, double-buffered, [b][k]
__device__ float g_hT[NH][NB];               // final h, [j][b] for hyper kernel
__device__ float g_A [NB * NH * NH];         // A^T per batch: [b][k][h]
__device__ float g_Bm[NB * NI * NH];         // Bm per batch:  [b][i][h]
__device__ float g_C [NB * NH];              // [b][h]
__device__ float g_Bu[(size_t)NB * NT * NH]; // [b][t][h]

// -------------------- f32x2 helpers ----------------------------------------
__device__ __forceinline__ unsigned long long pk2(float lo, float hi) {
    unsigned long long r;
    asm("mov.b64 %0, {%1, %2};" : "=l"(r) : "f"(lo), "f"(hi));
    return r;
}
__device__ __forceinline__ void upk2(unsigned long long v, float& lo, float& hi) {
    asm("mov.b64 {%0, %1}, %2;" : "=f"(lo), "=f"(hi) : "l"(v));
}
#define FMA2(acc, a, b) \
    asm("fma.rn.f32x2 %0, %1, %2, %0;" : "+l"(acc) : "l"(a), "l"(b))

// -------------------- persistent GRU scan ---------------------------------
// grid 128 = 16 clusters x 8 CTAs, 256 threads. Cluster cl owns batches
// [cl*16, cl*16+16). CTA rank owns hidden [rank*32, rank*32+32) for all 3
// gate strips; those 96 Whh rows live in smem (interleaved f32x2 layout) for
// the whole scan. h exchanged through L2 each step.
__global__ void __launch_bounds__(256, 1) __cluster_dims__(CLS, 1, 1)
gru_scan_kernel(const float* __restrict__ u,
                const float* __restrict__ gWih,  // [768,17]
                const float* __restrict__ gWhh,  // [768,256]
                const float* __restrict__ gbih,
                const float* __restrict__ gbhh)
{
    extern __shared__ float sm[];
    float* sW  = sm;             // 3*128*16 ulonglong2: ((s*128+kk2)*16+hp) -> {w(k0,h0),w(k0,h1),w(k1,h0),w(k1,h1)}
    float* sWi = sm + 24576;     // 3*17*16 ull: ((s*17+ii)*16+hp) -> {w(ii,h0),w(ii,h1)}
    float* sh  = sm + 26208;     // [16][SHS] h, [b][k]
    float* su  = sm + 30368;     // [16][20] inputs this step

    const int tid   = threadIdx.x;
    const int rank  = blockIdx.x & (CLS - 1);
    const int cl    = blockIdx.x / CLS;
    const int batch0 = cl * BG;
    const int hb    = rank * HPC;

    const int hp = tid & 15;     // hidden pair 0..15
    const int bb = tid >> 4;     // batch 0..15

    // ---- one-time weight load: Whh rows for this CTA, interleaved ----
    for (int idx = tid; idx < 3 * HPC * NH; idx += 256) {
        int r = idx >> 8, k = idx & 255;
        int s = r >> 5, hh = r & 31;
        float w = gWhh[(size_t)(s * NH + hb + hh) * NH + k];
        int kk2 = k >> 1, kb = k & 1, hpd = hh >> 1, hbit = hh & 1;
        sW[(((s * 128 + kk2) * 16 + hpd) << 2) + (kb << 1) + hbit] = w;
    }
    for (int idx = tid; idx < 3 * HPC * NIX; idx += 256) {
        int r = idx / NIX, ii = idx % NIX;
        int s = r >> 5, hh = r & 31;
        float w = gWih[(s * NH + hb + hh) * NIX + ii];
        sWi[((s * 17 + ii) * 16 + (hh >> 1)) * 2 + (hh & 1)] = w;
    }
    for (int idx = tid; idx < BG * SHS; idx += 256) sh[idx] = 0.f;

    // ---- packed biases for this thread's hidden pair ----
    const int g0 = hb + 2 * hp, g1 = g0 + 1;
    const unsigned long long bR2  = pk2(gbih[0*NH+g0] + gbhh[0*NH+g0],
                                        gbih[0*NH+g1] + gbhh[0*NH+g1]);
    const unsigned long long bZ2  = pk2(gbih[1*NH+g0] + gbhh[1*NH+g0],
                                        gbih[1*NH+g1] + gbhh[1*NH+g1]);
    const unsigned long long bNi2 = pk2(gbih[2*NH+g0], gbih[2*NH+g1]);
    const unsigned long long bNh2 = pk2(gbhh[2*NH+g0], gbhh[2*NH+g1]);

    const ulonglong2* wB = (const ulonglong2*)sW;
    const unsigned long long* wiB = (const unsigned long long*)sWi;
    const float* xrow = sh + bb * SHS;
    const float* srow = su + bb * 20;

    for (int t = 0; t < NT; t++) {
        // inputs for step t
        for (int idx = tid; idx < BG * NIX; idx += 256) {
            int b = idx / NIX, ii = idx % NIX;
            su[b * 20 + ii] = u[(size_t)(batch0 + b) * (NT * NIX) + t * NIX + ii];
        }
        __syncthreads();

        unsigned long long accR = bR2, accZ = bZ2, accNi = bNi2, accNh = bNh2;

        #pragma unroll 2
        for (int kk2 = 0; kk2 < 128; kk2 += 2) {
            float4 xv = *(const float4*)(xrow + 2 * kk2);
            unsigned long long x0 = pk2(xv.x, xv.x);
            unsigned long long x1 = pk2(xv.y, xv.y);
            unsigned long long x2 = pk2(xv.z, xv.z);
            unsigned long long x3 = pk2(xv.w, xv.w);
            ulonglong2 wr0 = wB[(0 * 128 + kk2    ) * 16 + hp];
            ulonglong2 wr1 = wB[(0 * 128 + kk2 + 1) * 16 + hp];
            ulonglong2 wz0 = wB[(1 * 128 + kk2    ) * 16 + hp];
            ulonglong2 wz1 = wB[(1 * 128 + kk2 + 1) * 16 + hp];
            ulonglong2 wn0 = wB[(2 * 128 + kk2    ) * 16 + hp];
            ulonglong2 wn1 = wB[(2 * 128 + kk2 + 1) * 16 + hp];
            FMA2(accR, wr0.x, x0); FMA2(accR, wr0.y, x1);
            FMA2(accR, wr1.x, x2); FMA2(accR, wr1.y, x3);
            FMA2(accZ, wz0.x, x0); FMA2(accZ, wz0.y, x1);
            FMA2(accZ, wz1.x, x2); FMA2(accZ, wz1.y, x3);
            FMA2(accNh, wn0.x, x0); FMA2(accNh, wn0.y, x1);
            FMA2(accNh, wn1.x, x2); FMA2(accNh, wn1.y, x3);
        }

        // input contribution
        #pragma unroll
        for (int ii = 0; ii < NIX; ii++) {
            float xs = srow[ii];
            unsigned long long x2i = pk2(xs, xs);
            FMA2(accR,  wiB[(0 * 17 + ii) * 16 + hp], x2i);
            FMA2(accZ,  wiB[(1 * 17 + ii) * 16 + hp], x2i);
            FMA2(accNi, wiB[(2 * 17 + ii) * 16 + hp], x2i);
        }

        // gate nonlinearity + h update for (g0,g1) x batch bb
        float r0, r1, z0, z1, ni0, ni1, nh0, nh1;
        upk2(accR, r0, r1); upk2(accZ, z0, z1);
        upk2(accNi, ni0, ni1); upk2(accNh, nh0, nh1);
        float ho0 = xrow[g0], ho1 = xrow[g1];
        float rr0 = 1.f / (1.f + expf(-r0)), rr1 = 1.f / (1.f + expf(-r1));
        float zz0 = 1.f / (1.f + expf(-z0)), zz1 = 1.f / (1.f + expf(-z1));
        float n0 = tanhf(ni0 + rr0 * nh0),   n1 = tanhf(ni1 + rr1 * nh1);
        float hn0 = (1.f - zz0) * n0 + zz0 * ho0;
        float hn1 = (1.f - zz1) * n1 + zz1 * ho1;

        const int par = t & 1;
        __stcg((float2*)&g_hx[par][batch0 + bb][g0], make_float2(hn0, hn1));
        if (t == NT - 1) {
            g_hT[g0][batch0 + bb] = hn0;
            g_hT[g1][batch0 + bb] = hn1;
        }
        __threadfence();
        asm volatile("barrier.cluster.arrive.aligned;" ::: "memory");
        asm volatile("barrier.cluster.wait.aligned;"   ::: "memory");

        // reload full h (all 256 hidden for our 16 batches)
        const float* gsrc = &g_hx[par][batch0][0];
        for (int idx = tid; idx < BG * NH; idx += 256) {
            int b = idx >> 8, k = idx & 255;
            sh[b * SHS + k] = __ldcg(gsrc + b * NH + k);
        }
        // next iteration's __syncthreads (after su load) orders sh/su writes
    }
}

// -------------------- hypernetwork GEMM ---------------------------------
__global__ void hyper_kernel(const float* __restrict__ Wage,
                             const float* __restrict__ bage,
                             const float* __restrict__ Wih,   // [256,16]
                             const float* __restrict__ Whh,   // [256,256]
                             const float* __restrict__ bih,
                             const float* __restrict__ bhh,
                             const float* __restrict__ hT)    // [j][b]
{
    __shared__ float sWg[64][33];
    __shared__ float sh[32][64];

    const int d0 = blockIdx.x * 64;
    const int b0 = blockIdx.y * 64;
    const int bb0 = (threadIdx.x & 15) * 4;
    const int dd0 = (threadIdx.x >> 4) * 4;

    float acc[4][4] = {};

    for (int k0 = 0; k0 < NH; k0 += 32) {
        __syncthreads();
        for (int i = threadIdx.x; i < 2048; i += 256) {
            int dd = i >> 5, kk = i & 31;
            sWg[dd][kk] = Wage[(size_t)(d0 + dd) * NH + k0 + kk];
        }
        for (int i = threadIdx.x; i < 2048; i += 256) {
            int kk = i >> 6, bb = i & 63;
            sh[kk][bb] = hT[(k0 + kk) * NB + b0 + bb];
        }
        __syncthreads();
        #pragma unroll 8
        for (int kk = 0; kk < 32; kk++) {
            float4 hv = *(const float4*)&sh[kk][bb0];
            #pragma unroll
            for (int di = 0; di < 4; di++) {
                float wv = sWg[dd0 + di][kk];
                acc[di][0] = fmaf(wv, hv.x, acc[di][0]);
                acc[di][1] = fmaf(wv, hv.y, acc[di][1]);
                acc[di][2] = fmaf(wv, hv.z, acc[di][2]);
                acc[di][3] = fmaf(wv, hv.w, acc[di][3]);
            }
        }
    }

    #pragma unroll
    for (int di = 0; di < 4; di++) {
        int d = d0 + dd0 + di;
        float base = bage[d];
        #pragma unroll
        for (int bi = 0; bi < 4; bi++) {
            int b = b0 + bb0 + bi;
            float v = acc[di][bi] + base;
            if (d < NI * NH) {
                int hr = d >> 4, ii = d & 15;
                g_Bm[(size_t)b * (NI * NH) + ii * NH + hr] = v + Wih[d];
            } else if (d < NI * NH + NH * NH) {
                int dd = d - NI * NH;
                int hr = dd >> 8, kk = dd & 255;
                g_A[(size_t)b * (NH * NH) + kk * NH + hr] = v + Whh[dd];
            } else {
                int j = d - (NI * NH + NH * NH);
                g_C[b * NH + j] = v + bih[j] + bhh[j];
            }
        }
    }
}

// -------------------- Bu = einsum('bhi,bti->bth') -----------------------
__global__ void bu_kernel(const float* __restrict__ u)
{
    __shared__ float sBm[NI][NH];
    __shared__ float su2[32][NI];

    const int b = blockIdx.x;
    const int tblk = blockIdx.y * 32;
    const int h = threadIdx.x;

    for (int i = threadIdx.x; i < NI * NH; i += 256) {
        sBm[i >> 8][i & 255] = g_Bm[(size_t)b * (NI * NH) + i];
    }
    for (int i = threadIdx.x; i < 32 * NI; i += 256) {
        int tt = i >> 4, ii = i & 15;
        int t = tblk + tt;
        su2[tt][ii] = (t < NT) ? u[(size_t)b * (NT * NIX) + t * NIX + ii] : 0.f;
    }
    __syncthreads();

    for (int tt = 0; tt < 32; tt++) {
        int t = tblk + tt;
        if (t >= NT) break;
        float acc = 0.f;
        #pragma unroll
        for (int ii = 0; ii < NI; ii++)
            acc = fmaf(sBm[ii][h], su2[tt][ii], acc);
        g_Bu[((size_t)b * NT + t) * NH + h] = acc;
    }
}

// -------------------- fixed point + Euler + output ----------------------
#define SMEM_K 128
#define REG_K  128

__device__ __forceinline__ float dotA(const float* __restrict__ sA,
                                      const float* __restrict__ Areg,
                                      const float* __restrict__ sx,
                                      int h)
{
    float acc = 0.f;
    const float4* sx4 = (const float4*)sx;
    #pragma unroll 4
    for (int k4 = 0; k4 < SMEM_K / 4; k4++) {
        float4 xv = sx4[k4];
        int kb = k4 * 4;
        acc = fmaf(sA[(kb + 0) * NH + h], xv.x, acc);
        acc = fmaf(sA[(kb + 1) * NH + h], xv.y, acc);
        acc = fmaf(sA[(kb + 2) * NH + h], xv.z, acc);
        acc = fmaf(sA[(kb + 3) * NH + h], xv.w, acc);
    }
    #pragma unroll
    for (int k4 = 0; k4 < REG_K / 4; k4++) {
        float4 xv = sx4[SMEM_K / 4 + k4];
        acc = fmaf(Areg[k4 * 4 + 0], xv.x, acc);
        acc = fmaf(Areg[k4 * 4 + 1], xv.y, acc);
        acc = fmaf(Areg[k4 * 4 + 2], xv.z, acc);
        acc = fmaf(Areg[k4 * 4 + 3], xv.w, acc);
    }
    return acc;
}

__global__ void __launch_bounds__(256, 1)
fpeuler_kernel(const float* __restrict__ tau,
               const float* __restrict__ Wout,  // [8,256]
               const float* __restrict__ bout,
               float* __restrict__ out)         // [b][t][8]
{
    extern __shared__ float sA[];                 // [SMEM_K][256]
    __shared__ __align__(16) float sx[NH];

    const int b = blockIdx.x;
    const int h = threadIdx.x;
    const float* __restrict__ Ab = g_A + (size_t)b * (NH * NH);

    for (int idx = h; idx < SMEM_K * NH; idx += 256)
        sA[idx] = Ab[idx];
    float Areg[REG_K];
    #pragma unroll
    for (int r = 0; r < REG_K; r++)
        Areg[r] = Ab[(SMEM_K + r) * NH + h];

    const float Cv  = g_C[b * NH + h];
    const float et  = expf(tau[h]);
    const float* __restrict__ BuB = g_Bu + (size_t)b * NT * NH + h;
    const float bu0 = BuB[0];

    const int w = h >> 5, l = h & 31;
    float wo[8];
    #pragma unroll
    for (int j = 0; j < 8; j++) wo[j] = Wout[w * NH + l * 8 + j];
    const float bo = bout[w];

    float myx = 0.f;
    sx[h] = 0.f;
    __syncthreads();

    for (int it = 0; it < FPIT; it++) {
        float acc = dotA(sA, Areg, sx, h);
        float xn = et * tanhf(acc + bu0 + Cv);
        __syncthreads();
        sx[h] = xn;
        myx = xn;
        __syncthreads();
    }

    {
        const float4* p = (const float4*)(sx + l * 8);
        float4 v0 = p[0], v1 = p[1];
        float a = wo[0] * v0.x;
        a = fmaf(wo[1], v0.y, a); a = fmaf(wo[2], v0.z, a); a = fmaf(wo[3], v0.w, a);
        a = fmaf(wo[4], v1.x, a); a = fmaf(wo[5], v1.y, a);
        a = fmaf(wo[6], v1.z, a); a = fmaf(wo[7], v1.w, a);
        #pragma unroll
        for (int off = 16; off; off >>= 1) a += __shfl_xor_sync(0xffffffffu, a, off);
        if (l == 0) out[((size_t)b * NT + 0) * NO + w] = a + bo;
    }

    float bu = bu0;
    for (int k = 0; k < NT - 1; k++) {
        float bu_nx = (k < NT - 2) ? BuB[(size_t)(k + 1) * NH] : 0.f;
        float acc = dotA(sA, Areg, sx, h);
        float xn = myx + tanhf(acc + bu + Cv) - myx / et;
        __syncthreads();
        sx[h] = xn;
        myx = xn;
        __syncthreads();

        const float4* p = (const float4*)(sx + l * 8);
        float4 v0 = p[0], v1 = p[1];
        float a = wo[0] * v0.x;
        a = fmaf(wo[1], v0.y, a); a = fmaf(wo[2], v0.z, a); a = fmaf(wo[3], v0.w, a);
        a = fmaf(wo[4], v1.x, a); a = fmaf(wo[5], v1.y, a);
        a = fmaf(wo[6], v1.z, a); a = fmaf(wo[7], v1.w, a);
        #pragma unroll
        for (int off = 16; off; off >>= 1) a += __shfl_xor_sync(0xffffffffu, a, off);
        if (l == 0) out[((size_t)b * NT + (k + 1)) * NO + w] = a + bo;

        bu = bu_nx;
    }
}

// -------------------- launch --------------------------------------------
extern "C" void kernel_launch(void* const* d_in, const int* in_sizes, int n_in,
                              void* d_out, int out_size)
{
    const float* u    = (const float*)d_in[0];
    const float* gWih = (const float*)d_in[1];
    const float* gWhh = (const float*)d_in[2];
    const float* gbih = (const float*)d_in[3];
    const float* gbhh = (const float*)d_in[4];
    const float* Wage = (const float*)d_in[5];
    const float* bage = (const float*)d_in[6];
    const float* Wih  = (const float*)d_in[7];
    const float* Whh  = (const float*)d_in[8];
    const float* bih  = (const float*)d_in[9];
    const float* bhh  = (const float*)d_in[10];
    const float* tau  = (const float*)d_in[11];
    const float* Wout = (const float*)d_in[12];
    const float* bout = (const float*)d_in[13];
    float* out = (float*)d_out;

    // persistent GRU scan: one kernel, 16 clusters x 8 CTAs
    const int GRU_SMEM = (24576 + 1632 + BG * SHS + BG * 20) * (int)sizeof(float);
    cudaFuncSetAttribute(gru_scan_kernel,
                         cudaFuncAttributeMaxDynamicSharedMemorySize, GRU_SMEM);
    gru_scan_kernel<<<128, 256, GRU_SMEM>>>(u, gWih, gWhh, gbih, gbhh);

    float* hT = nullptr;
    cudaGetSymbolAddress((void**)&hT, g_hT);

    hyper_kernel<<<dim3(ND / 64, NB / 64), 256>>>(Wage, bage, Wih, Whh, bih, bhh, hT);

    bu_kernel<<<dim3(NB, (NT + 31) / 32), 256>>>(u);

    cudaFuncSetAttribute(fpeuler_kernel,
                         cudaFuncAttributeMaxDynamicSharedMemorySize,
                         SMEM_K * NH * (int)sizeof(float));
    fpeuler_kernel<<<NB, 256, SMEM_K * NH * sizeof(float)>>>(tau, Wout, bout, out);
}

// round 4
// speedup vs baseline: 1.2690x; 1.0003x over previous
#include <cuda_runtime.h>
#include <cuda_bf16.h>
#include <math.h>

// Problem constants
#define NB    256   // BATCH
#define NH    256   // NHIDDEN == NHAGE
#define NI    16    // NINPUT
#define NIX   17    // NINPUT + 1
#define NT    501   // NSTEP
#define ND    69888 // NI*NH + NH*NH + NH
#define NO    8     // NOUT
#define FPIT  100

// GRU persistent-cluster config
#define CLS   8     // CTAs per cluster
#define BG    16    // batches per cluster
#define HPC   32    // hidden indices per CTA
#define SHS   260   // padded h-row stride (floats)

// -------------------- device scratch --------------------------------------
__device__ float g_hx[2][NB][NH];            // h exchange, double-buffered, [b][k]
__device__ float g_hT[NH][NB];               // final h, [j][b] for hyper kernel
__device__ float g_A [NB * NH * NH];         // A^T per batch: [b][k][h]
__device__ float g_Bm[NB * NI * NH];         // Bm per batch:  [b][i][h]
__device__ float g_C [NB * NH];              // [b][h]
__device__ float g_Bu[(size_t)NB * NT * NH]; // [b][t][h]

// -------------------- f32x2 helpers ----------------------------------------
__device__ __forceinline__ unsigned long long pk2(float lo, float hi) {
    unsigned long long r;
    asm("mov.b64 %0, {%1, %2};" : "=l"(r) : "f"(lo), "f"(hi));
    return r;
}
__device__ __forceinline__ void upk2(unsigned long long v, float& lo, float& hi) {
    asm("mov.b64 {%0, %1}, %2;" : "=f"(lo), "=f"(hi) : "l"(v));
}
#define FMA2(acc, a, b) \
    asm("fma.rn.f32x2 %0, %1, %2, %0;" : "+l"(acc) : "l"(a), "l"(b))

// -------------------- persistent GRU scan ---------------------------------
// grid 128 = 16 clusters x 8 CTAs, 256 threads. Cluster cl owns batches
// [cl*16, cl*16+16). CTA rank owns hidden [rank*32, rank*32+32) for all 3
// gate strips; those 96 Whh rows live in smem (interleaved f32x2 layout) for
// the whole scan. h exchanged through L2 each step.
__global__ void __launch_bounds__(256, 1) __cluster_dims__(CLS, 1, 1)
gru_scan_kernel(const float* __restrict__ u,
                const float* __restrict__ gWih,  // [768,17]
                const float* __restrict__ gWhh,  // [768,256]
                const float* __restrict__ gbih,
                const float* __restrict__ gbhh)
{
    extern __shared__ float sm[];
    float* sW  = sm;             // 3*128*16 ulonglong2: ((s*128+kk2)*16+hp) -> {w(k0,h0),w(k0,h1),w(k1,h0),w(k1,h1)}
    float* sWi = sm + 24576;     // 3*17*16 ull: ((s*17+ii)*16+hp) -> {w(ii,h0),w(ii,h1)}
    float* sh  = sm + 26208;     // [16][SHS] h, [b][k]
    float* su  = sm + 30368;     // [16][20] inputs this step

    const int tid   = threadIdx.x;
    const int rank  = blockIdx.x & (CLS - 1);
    const int cl    = blockIdx.x / CLS;
    const int batch0 = cl * BG;
    const int hb    = rank * HPC;

    const int hp = tid & 15;     // hidden pair 0..15
    const int bb = tid >> 4;     // batch 0..15

    // ---- one-time weight load: Whh rows for this CTA, interleaved ----
    for (int idx = tid; idx < 3 * HPC * NH; idx += 256) {
        int r = idx >> 8, k = idx & 255;
        int s = r >> 5, hh = r & 31;
        float w = gWhh[(size_t)(s * NH + hb + hh) * NH + k];
        int kk2 = k >> 1, kb = k & 1, hpd = hh >> 1, hbit = hh & 1;
        sW[(((s * 128 + kk2) * 16 + hpd) << 2) + (kb << 1) + hbit] = w;
    }
    for (int idx = tid; idx < 3 * HPC * NIX; idx += 256) {
        int r = idx / NIX, ii = idx % NIX;
        int s = r >> 5, hh = r & 31;
        float w = gWih[(s * NH + hb + hh) * NIX + ii];
        sWi[((s * 17 + ii) * 16 + (hh >> 1)) * 2 + (hh & 1)] = w;
    }
    for (int idx = tid; idx < BG * SHS; idx += 256) sh[idx] = 0.f;

    // ---- packed biases for this thread's hidden pair ----
    const int g0 = hb + 2 * hp, g1 = g0 + 1;
    const unsigned long long bR2  = pk2(gbih[0*NH+g0] + gbhh[0*NH+g0],
                                        gbih[0*NH+g1] + gbhh[0*NH+g1]);
    const unsigned long long bZ2  = pk2(gbih[1*NH+g0] + gbhh[1*NH+g0],
                                        gbih[1*NH+g1] + gbhh[1*NH+g1]);
    const unsigned long long bNi2 = pk2(gbih[2*NH+g0], gbih[2*NH+g1]);
    const unsigned long long bNh2 = pk2(gbhh[2*NH+g0], gbhh[2*NH+g1]);

    const ulonglong2* wB = (const ulonglong2*)sW;
    const unsigned long long* wiB = (const unsigned long long*)sWi;
    const float* xrow = sh + bb * SHS;
    const float* srow = su + bb * 20;

    for (int t = 0; t < NT; t++) {
        // inputs for step t
        for (int idx = tid; idx < BG * NIX; idx += 256) {
            int b = idx / NIX, ii = idx % NIX;
            su[b * 20 + ii] = u[(size_t)(batch0 + b) * (NT * NIX) + t * NIX + ii];
        }
        __syncthreads();

        unsigned long long accR = bR2, accZ = bZ2, accNi = bNi2, accNh = bNh2;

        #pragma unroll 2
        for (int kk2 = 0; kk2 < 128; kk2 += 2) {
            float4 xv = *(const float4*)(xrow + 2 * kk2);
            unsigned long long x0 = pk2(xv.x, xv.x);
            unsigned long long x1 = pk2(xv.y, xv.y);
            unsigned long long x2 = pk2(xv.z, xv.z);
            unsigned long long x3 = pk2(xv.w, xv.w);
            ulonglong2 wr0 = wB[(0 * 128 + kk2    ) * 16 + hp];
            ulonglong2 wr1 = wB[(0 * 128 + kk2 + 1) * 16 + hp];
            ulonglong2 wz0 = wB[(1 * 128 + kk2    ) * 16 + hp];
            ulonglong2 wz1 = wB[(1 * 128 + kk2 + 1) * 16 + hp];
            ulonglong2 wn0 = wB[(2 * 128 + kk2    ) * 16 + hp];
            ulonglong2 wn1 = wB[(2 * 128 + kk2 + 1) * 16 + hp];
            FMA2(accR, wr0.x, x0); FMA2(accR, wr0.y, x1);
            FMA2(accR, wr1.x, x2); FMA2(accR, wr1.y, x3);
            FMA2(accZ, wz0.x, x0); FMA2(accZ, wz0.y, x1);
            FMA2(accZ, wz1.x, x2); FMA2(accZ, wz1.y, x3);
            FMA2(accNh, wn0.x, x0); FMA2(accNh, wn0.y, x1);
            FMA2(accNh, wn1.x, x2); FMA2(accNh, wn1.y, x3);
        }

        // input contribution
        #pragma unroll
        for (int ii = 0; ii < NIX; ii++) {
            float xs = srow[ii];
            unsigned long long x2i = pk2(xs, xs);
            FMA2(accR,  wiB[(0 * 17 + ii) * 16 + hp], x2i);
            FMA2(accZ,  wiB[(1 * 17 + ii) * 16 + hp], x2i);
            FMA2(accNi, wiB[(2 * 17 + ii) * 16 + hp], x2i);
        }

        // gate nonlinearity + h update for (g0,g1) x batch bb
        float r0, r1, z0, z1, ni0, ni1, nh0, nh1;
        upk2(accR, r0, r1); upk2(accZ, z0, z1);
        upk2(accNi, ni0, ni1); upk2(accNh, nh0, nh1);
        float ho0 = xrow[g0], ho1 = xrow[g1];
        float rr0 = 1.f / (1.f + expf(-r0)), rr1 = 1.f / (1.f + expf(-r1));
        float zz0 = 1.f / (1.f + expf(-z0)), zz1 = 1.f / (1.f + expf(-z1));
        float n0 = tanhf(ni0 + rr0 * nh0),   n1 = tanhf(ni1 + rr1 * nh1);
        float hn0 = (1.f - zz0) * n0 + zz0 * ho0;
        float hn1 = (1.f - zz1) * n1 + zz1 * ho1;

        const int par = t & 1;
        __stcg((float2*)&g_hx[par][batch0 + bb][g0], make_float2(hn0, hn1));
        if (t == NT - 1) {
            g_hT[g0][batch0 + bb] = hn0;
            g_hT[g1][batch0 + bb] = hn1;
        }
        __threadfence();
        asm volatile("barrier.cluster.arrive.aligned;" ::: "memory");
        asm volatile("barrier.cluster.wait.aligned;"   ::: "memory");

        // reload full h (all 256 hidden for our 16 batches)
        const float* gsrc = &g_hx[par][batch0][0];
        for (int idx = tid; idx < BG * NH; idx += 256) {
            int b = idx >> 8, k = idx & 255;
            sh[b * SHS + k] = __ldcg(gsrc + b * NH + k);
        }
        // next iteration's __syncthreads (after su load) orders sh/su writes
    }
}

// -------------------- hypernetwork GEMM ---------------------------------
__global__ void hyper_kernel(const float* __restrict__ Wage,
                             const float* __restrict__ bage,
                             const float* __restrict__ Wih,   // [256,16]
                             const float* __restrict__ Whh,   // [256,256]
                             const float* __restrict__ bih,
                             const float* __restrict__ bhh,
                             const float* __restrict__ hT)    // [j][b]
{
    __shared__ float sWg[64][33];
    __shared__ float sh[32][64];

    const int d0 = blockIdx.x * 64;
    const int b0 = blockIdx.y * 64;
    const int bb0 = (threadIdx.x & 15) * 4;
    const int dd0 = (threadIdx.x >> 4) * 4;

    float acc[4][4] = {};

    for (int k0 = 0; k0 < NH; k0 += 32) {
        __syncthreads();
        for (int i = threadIdx.x; i < 2048; i += 256) {
            int dd = i >> 5, kk = i & 31;
            sWg[dd][kk] = Wage[(size_t)(d0 + dd) * NH + k0 + kk];
        }
        for (int i = threadIdx.x; i < 2048; i += 256) {
            int kk = i >> 6, bb = i & 63;
            sh[kk][bb] = hT[(k0 + kk) * NB + b0 + bb];
        }
        __syncthreads();
        #pragma unroll 8
        for (int kk = 0; kk < 32; kk++) {
            float4 hv = *(const float4*)&sh[kk][bb0];
            #pragma unroll
            for (int di = 0; di < 4; di++) {
                float wv = sWg[dd0 + di][kk];
                acc[di][0] = fmaf(wv, hv.x, acc[di][0]);
                acc[di][1] = fmaf(wv, hv.y, acc[di][1]);
                acc[di][2] = fmaf(wv, hv.z, acc[di][2]);
                acc[di][3] = fmaf(wv, hv.w, acc[di][3]);
            }
        }
    }

    #pragma unroll
    for (int di = 0; di < 4; di++) {
        int d = d0 + dd0 + di;
        float base = bage[d];
        #pragma unroll
        for (int bi = 0; bi < 4; bi++) {
            int b = b0 + bb0 + bi;
            float v = acc[di][bi] + base;
            if (d < NI * NH) {
                int hr = d >> 4, ii = d & 15;
                g_Bm[(size_t)b * (NI * NH) + ii * NH + hr] = v + Wih[d];
            } else if (d < NI * NH + NH * NH) {
                int dd = d - NI * NH;
                int hr = dd >> 8, kk = dd & 255;
                g_A[(size_t)b * (NH * NH) + kk * NH + hr] = v + Whh[dd];
            } else {
                int j = d - (NI * NH + NH * NH);
                g_C[b * NH + j] = v + bih[j] + bhh[j];
            }
        }
    }
}

// -------------------- Bu = einsum('bhi,bti->bth') -----------------------
__global__ void bu_kernel(const float* __restrict__ u)
{
    __shared__ float sBm[NI][NH];
    __shared__ float su2[32][NI];

    const int b = blockIdx.x;
    const int tblk = blockIdx.y * 32;
    const int h = threadIdx.x;

    for (int i = threadIdx.x; i < NI * NH; i += 256) {
        sBm[i >> 8][i & 255] = g_Bm[(size_t)b * (NI * NH) + i];
    }
    for (int i = threadIdx.x; i < 32 * NI; i += 256) {
        int tt = i >> 4, ii = i & 15;
        int t = tblk + tt;
        su2[tt][ii] = (t < NT) ? u[(size_t)b * (NT * NIX) + t * NIX + ii] : 0.f;
    }
    __syncthreads();

    for (int tt = 0; tt < 32; tt++) {
        int t = tblk + tt;
        if (t >= NT) break;
        float acc = 0.f;
        #pragma unroll
        for (int ii = 0; ii < NI; ii++)
            acc = fmaf(sBm[ii][h], su2[tt][ii], acc);
        g_Bu[((size_t)b * NT + t) * NH + h] = acc;
    }
}

// -------------------- fixed point + Euler + output ----------------------
#define SMEM_K 128
#define REG_K  128

__device__ __forceinline__ float dotA(const float* __restrict__ sA,
                                      const float* __restrict__ Areg,
                                      const float* __restrict__ sx,
                                      int h)
{
    float acc = 0.f;
    const float4* sx4 = (const float4*)sx;
    #pragma unroll 4
    for (int k4 = 0; k4 < SMEM_K / 4; k4++) {
        float4 xv = sx4[k4];
        int kb = k4 * 4;
        acc = fmaf(sA[(kb + 0) * NH + h], xv.x, acc);
        acc = fmaf(sA[(kb + 1) * NH + h], xv.y, acc);
        acc = fmaf(sA[(kb + 2) * NH + h], xv.z, acc);
        acc = fmaf(sA[(kb + 3) * NH + h], xv.w, acc);
    }
    #pragma unroll
    for (int k4 = 0; k4 < REG_K / 4; k4++) {
        float4 xv = sx4[SMEM_K / 4 + k4];
        acc = fmaf(Areg[k4 * 4 + 0], xv.x, acc);
        acc = fmaf(Areg[k4 * 4 + 1], xv.y, acc);
        acc = fmaf(Areg[k4 * 4 + 2], xv.z, acc);
        acc = fmaf(Areg[k4 * 4 + 3], xv.w, acc);
    }
    return acc;
}

__global__ void __launch_bounds__(256, 1)
fpeuler_kernel(const float* __restrict__ tau,
               const float* __restrict__ Wout,  // [8,256]
               const float* __restrict__ bout,
               float* __restrict__ out)         // [b][t][8]
{
    extern __shared__ float sA[];                 // [SMEM_K][256]
    __shared__ __align__(16) float sx[NH];

    const int b = blockIdx.x;
    const int h = threadIdx.x;
    const float* __restrict__ Ab = g_A + (size_t)b * (NH * NH);

    for (int idx = h; idx < SMEM_K * NH; idx += 256)
        sA[idx] = Ab[idx];
    float Areg[REG_K];
    #pragma unroll
    for (int r = 0; r < REG_K; r++)
        Areg[r] = Ab[(SMEM_K + r) * NH + h];

    const float Cv  = g_C[b * NH + h];
    const float et  = expf(tau[h]);
    const float* __restrict__ BuB = g_Bu + (size_t)b * NT * NH + h;
    const float bu0 = BuB[0];

    const int w = h >> 5, l = h & 31;
    float wo[8];
    #pragma unroll
    for (int j = 0; j < 8; j++) wo[j] = Wout[w * NH + l * 8 + j];
    const float bo = bout[w];

    float myx = 0.f;
    sx[h] = 0.f;
    __syncthreads();

    for (int it = 0; it < FPIT; it++) {
        float acc = dotA(sA, Areg, sx, h);
        float xn = et * tanhf(acc + bu0 + Cv);
        __syncthreads();
        sx[h] = xn;
        myx = xn;
        __syncthreads();
    }

    {
        const float4* p = (const float4*)(sx + l * 8);
        float4 v0 = p[0], v1 = p[1];
        float a = wo[0] * v0.x;
        a = fmaf(wo[1], v0.y, a); a = fmaf(wo[2], v0.z, a); a = fmaf(wo[3], v0.w, a);
        a = fmaf(wo[4], v1.x, a); a = fmaf(wo[5], v1.y, a);
        a = fmaf(wo[6], v1.z, a); a = fmaf(wo[7], v1.w, a);
        #pragma unroll
        for (int off = 16; off; off >>= 1) a += __shfl_xor_sync(0xffffffffu, a, off);
        if (l == 0) out[((size_t)b * NT + 0) * NO + w] = a + bo;
    }

    float bu = bu0;
    for (int k = 0; k < NT - 1; k++) {
        float bu_nx = (k < NT - 2) ? BuB[(size_t)(k + 1) * NH] : 0.f;
        float acc = dotA(sA, Areg, sx, h);
        float xn = myx + tanhf(acc + bu + Cv) - myx / et;
        __syncthreads();
        sx[h] = xn;
        myx = xn;
        __syncthreads();

        const float4* p = (const float4*)(sx + l * 8);
        float4 v0 = p[0], v1 = p[1];
        float a = wo[0] * v0.x;
        a = fmaf(wo[1], v0.y, a); a = fmaf(wo[2], v0.z, a); a = fmaf(wo[3], v0.w, a);
        a = fmaf(wo[4], v1.x, a); a = fmaf(wo[5], v1.y, a);
        a = fmaf(wo[6], v1.z, a); a = fmaf(wo[7], v1.w, a);
        #pragma unroll
        for (int off = 16; off; off >>= 1) a += __shfl_xor_sync(0xffffffffu, a, off);
        if (l == 0) out[((size_t)b * NT + (k + 1)) * NO + w] = a + bo;

        bu = bu_nx;
    }
}

// -------------------- launch --------------------------------------------
extern "C" void kernel_launch(void* const* d_in, const int* in_sizes, int n_in,
                              void* d_out, int out_size)
{
    const float* u    = (const float*)d_in[0];
    const float* gWih = (const float*)d_in[1];
    const float* gWhh = (const float*)d_in[2];
    const float* gbih = (const float*)d_in[3];
    const float* gbhh = (const float*)d_in[4];
    const float* Wage = (const float*)d_in[5];
    const float* bage = (const float*)d_in[6];
    const float* Wih  = (const float*)d_in[7];
    const float* Whh  = (const float*)d_in[8];
    const float* bih  = (const float*)d_in[9];
    const float* bhh  = (const float*)d_in[10];
    const float* tau  = (const float*)d_in[11];
    const float* Wout = (const float*)d_in[12];
    const float* bout = (const float*)d_in[13];
    float* out = (float*)d_out;

    // persistent GRU scan: one kernel, 16 clusters x 8 CTAs
    const int GRU_SMEM = (24576 + 1632 + BG * SHS + BG * 20) * (int)sizeof(float);
    cudaFuncSetAttribute(gru_scan_kernel,
                         cudaFuncAttributeMaxDynamicSharedMemorySize, GRU_SMEM);
    gru_scan_kernel<<<128, 256, GRU_SMEM>>>(u, gWih, gWhh, gbih, gbhh);

    float* hT = nullptr;
    cudaGetSymbolAddress((void**)&hT, g_hT);

    hyper_kernel<<<dim3(ND / 64, NB / 64), 256>>>(Wage, bage, Wih, Whh, bih, bhh, hT);

    bu_kernel<<<dim3(NB, (NT + 31) / 32), 256>>>(u);

    cudaFuncSetAttribute(fpeuler_kernel,
                         cudaFuncAttributeMaxDynamicSharedMemorySize,
                         SMEM_K * NH * (int)sizeof(float));
    fpeuler_kernel<<<NB, 256, SMEM_K * NH * sizeof(float)>>>(tau, Wout, bout, out);
}

// round 5
// speedup vs baseline: 1.2701x; 1.0009x over previous
#include <cuda_runtime.h>
#include <cuda_bf16.h>
#include <math.h>

// Problem constants
#define NB    256   // BATCH
#define NH    256   // NHIDDEN == NHAGE
#define NI    16    // NINPUT
#define NIX   17    // NINPUT + 1
#define NT    501   // NSTEP
#define ND    69888 // NI*NH + NH*NH + NH
#define NO    8     // NOUT
#define FPIT  100

// GRU persistent-cluster config
#define CLS   8     // CTAs per cluster
#define BG    16    // batches per cluster
#define HPC   32    // hidden indices per CTA
#define SHS   260   // padded h-row stride (floats)

// -------------------- device scratch --------------------------------------
__device__ float g_hx[2][NB][NH];            // h exchange, double-buffered, [b][k]
__device__ float g_hT[NH][NB];               // final h, [j][b] for hyper kernel
__device__ float g_A [NB * NH * NH];         // A^T per batch: [b][k][h]
__device__ float g_Bm[NB * NI * NH];         // Bm per batch:  [b][i][h]
__device__ float g_C [NB * NH];              // [b][h]
__device__ float g_Bu[(size_t)NB * NT * NH]; // [b][t][h]

// -------------------- f32x2 helpers ----------------------------------------
__device__ __forceinline__ unsigned long long pk2(float lo, float hi) {
    unsigned long long r;
    asm("mov.b64 %0, {%1, %2};" : "=l"(r) : "f"(lo), "f"(hi));
    return r;
}
__device__ __forceinline__ void upk2(unsigned long long v, float& lo, float& hi) {
    asm("mov.b64 {%0, %1}, %2;" : "=f"(lo), "=f"(hi) : "l"(v));
}
#define FMA2(acc, a, b) \
    asm("fma.rn.f32x2 %0, %1, %2, %0;" : "+l"(acc) : "l"(a), "l"(b))

// -------------------- persistent GRU scan ---------------------------------
// grid 128 = 16 clusters x 8 CTAs, 256 threads. Cluster cl owns batches
// [cl*16, cl*16+16). CTA rank owns hidden [rank*32, rank*32+32) for all 3
// gate strips; those 96 Whh rows live in smem (interleaved f32x2 layout) for
// the whole scan. h exchanged through L2 each step.
__global__ void __launch_bounds__(256, 1) __cluster_dims__(CLS, 1, 1)
gru_scan_kernel(const float* __restrict__ u,
                const float* __restrict__ gWih,  // [768,17]
                const float* __restrict__ gWhh,  // [768,256]
                const float* __restrict__ gbih,
                const float* __restrict__ gbhh)
{
    extern __shared__ float sm[];
    float* sW  = sm;             // 3*128*16 ulonglong2: ((s*128+kk2)*16+hp) -> {w(k0,h0),w(k0,h1),w(k1,h0),w(k1,h1)}
    float* sWi = sm + 24576;     // 3*17*16 ull: ((s*17+ii)*16+hp) -> {w(ii,h0),w(ii,h1)}
    float* sh  = sm + 26208;     // [16][SHS] h, [b][k]
    float* su  = sm + 30368;     // [16][20] inputs this step

    const int tid   = threadIdx.x;
    const int rank  = blockIdx.x & (CLS - 1);
    const int cl    = blockIdx.x / CLS;
    const int batch0 = cl * BG;
    const int hb    = rank * HPC;

    const int hp = tid & 15;     // hidden pair 0..15
    const int bb = tid >> 4;     // batch 0..15

    // ---- one-time weight load: Whh rows for this CTA, interleaved ----
    for (int idx = tid; idx < 3 * HPC * NH; idx += 256) {
        int r = idx >> 8, k = idx & 255;
        int s = r >> 5, hh = r & 31;
        float w = gWhh[(size_t)(s * NH + hb + hh) * NH + k];
        int kk2 = k >> 1, kb = k & 1, hpd = hh >> 1, hbit = hh & 1;
        sW[(((s * 128 + kk2) * 16 + hpd) << 2) + (kb << 1) + hbit] = w;
    }
    for (int idx = tid; idx < 3 * HPC * NIX; idx += 256) {
        int r = idx / NIX, ii = idx % NIX;
        int s = r >> 5, hh = r & 31;
        float w = gWih[(s * NH + hb + hh) * NIX + ii];
        sWi[((s * 17 + ii) * 16 + (hh >> 1)) * 2 + (hh & 1)] = w;
    }
    for (int idx = tid; idx < BG * SHS; idx += 256) sh[idx] = 0.f;

    // ---- packed biases for this thread's hidden pair ----
    const int g0 = hb + 2 * hp, g1 = g0 + 1;
    const unsigned long long bR2  = pk2(gbih[0*NH+g0] + gbhh[0*NH+g0],
                                        gbih[0*NH+g1] + gbhh[0*NH+g1]);
    const unsigned long long bZ2  = pk2(gbih[1*NH+g0] + gbhh[1*NH+g0],
                                        gbih[1*NH+g1] + gbhh[1*NH+g1]);
    const unsigned long long bNi2 = pk2(gbih[2*NH+g0], gbih[2*NH+g1]);
    const unsigned long long bNh2 = pk2(gbhh[2*NH+g0], gbhh[2*NH+g1]);

    const ulonglong2* wB = (const ulonglong2*)sW;
    const unsigned long long* wiB = (const unsigned long long*)sWi;
    const float* xrow = sh + bb * SHS;
    const float* srow = su + bb * 20;

    for (int t = 0; t < NT; t++) {
        // inputs for step t
        for (int idx = tid; idx < BG * NIX; idx += 256) {
            int b = idx / NIX, ii = idx % NIX;
            su[b * 20 + ii] = u[(size_t)(batch0 + b) * (NT * NIX) + t * NIX + ii];
        }
        __syncthreads();

        unsigned long long accR = bR2, accZ = bZ2, accNi = bNi2, accNh = bNh2;

        #pragma unroll 2
        for (int kk2 = 0; kk2 < 128; kk2 += 2) {
            float4 xv = *(const float4*)(xrow + 2 * kk2);
            unsigned long long x0 = pk2(xv.x, xv.x);
            unsigned long long x1 = pk2(xv.y, xv.y);
            unsigned long long x2 = pk2(xv.z, xv.z);
            unsigned long long x3 = pk2(xv.w, xv.w);
            ulonglong2 wr0 = wB[(0 * 128 + kk2    ) * 16 + hp];
            ulonglong2 wr1 = wB[(0 * 128 + kk2 + 1) * 16 + hp];
            ulonglong2 wz0 = wB[(1 * 128 + kk2    ) * 16 + hp];
            ulonglong2 wz1 = wB[(1 * 128 + kk2 + 1) * 16 + hp];
            ulonglong2 wn0 = wB[(2 * 128 + kk2    ) * 16 + hp];
            ulonglong2 wn1 = wB[(2 * 128 + kk2 + 1) * 16 + hp];
            FMA2(accR, wr0.x, x0); FMA2(accR, wr0.y, x1);
            FMA2(accR, wr1.x, x2); FMA2(accR, wr1.y, x3);
            FMA2(accZ, wz0.x, x0); FMA2(accZ, wz0.y, x1);
            FMA2(accZ, wz1.x, x2); FMA2(accZ, wz1.y, x3);
            FMA2(accNh, wn0.x, x0); FMA2(accNh, wn0.y, x1);
            FMA2(accNh, wn1.x, x2); FMA2(accNh, wn1.y, x3);
        }

        // input contribution
        #pragma unroll
        for (int ii = 0; ii < NIX; ii++) {
            float xs = srow[ii];
            unsigned long long x2i = pk2(xs, xs);
            FMA2(accR,  wiB[(0 * 17 + ii) * 16 + hp], x2i);
            FMA2(accZ,  wiB[(1 * 17 + ii) * 16 + hp], x2i);
            FMA2(accNi, wiB[(2 * 17 + ii) * 16 + hp], x2i);
        }

        // gate nonlinearity + h update for (g0,g1) x batch bb
        float r0, r1, z0, z1, ni0, ni1, nh0, nh1;
        upk2(accR, r0, r1); upk2(accZ, z0, z1);
        upk2(accNi, ni0, ni1); upk2(accNh, nh0, nh1);
        float ho0 = xrow[g0], ho1 = xrow[g1];
        float rr0 = 1.f / (1.f + expf(-r0)), rr1 = 1.f / (1.f + expf(-r1));
        float zz0 = 1.f / (1.f + expf(-z0)), zz1 = 1.f / (1.f + expf(-z1));
        float n0 = tanhf(ni0 + rr0 * nh0),   n1 = tanhf(ni1 + rr1 * nh1);
        float hn0 = (1.f - zz0) * n0 + zz0 * ho0;
        float hn1 = (1.f - zz1) * n1 + zz1 * ho1;

        const int par = t & 1;
        __stcg((float2*)&g_hx[par][batch0 + bb][g0], make_float2(hn0, hn1));
        if (t == NT - 1) {
            g_hT[g0][batch0 + bb] = hn0;
            g_hT[g1][batch0 + bb] = hn1;
        }
        __threadfence();
        asm volatile("barrier.cluster.arrive.aligned;" ::: "memory");
        asm volatile("barrier.cluster.wait.aligned;"   ::: "memory");

        // reload full h (all 256 hidden for our 16 batches)
        const float* gsrc = &g_hx[par][batch0][0];
        for (int idx = tid; idx < BG * NH; idx += 256) {
            int b = idx >> 8, k = idx & 255;
            sh[b * SHS + k] = __ldcg(gsrc + b * NH + k);
        }
        // next iteration's __syncthreads (after su load) orders sh/su writes
    }
}

// -------------------- hypernetwork GEMM ---------------------------------
__global__ void hyper_kernel(const float* __restrict__ Wage,
                             const float* __restrict__ bage,
                             const float* __restrict__ Wih,   // [256,16]
                             const float* __restrict__ Whh,   // [256,256]
                             const float* __restrict__ bih,
                             const float* __restrict__ bhh,
                             const float* __restrict__ hT)    // [j][b]
{
    __shared__ float sWg[64][33];
    __shared__ float sh[32][64];

    const int d0 = blockIdx.x * 64;
    const int b0 = blockIdx.y * 64;
    const int bb0 = (threadIdx.x & 15) * 4;
    const int dd0 = (threadIdx.x >> 4) * 4;

    float acc[4][4] = {};

    for (int k0 = 0; k0 < NH; k0 += 32) {
        __syncthreads();
        for (int i = threadIdx.x; i < 2048; i += 256) {
            int dd = i >> 5, kk = i & 31;
            sWg[dd][kk] = Wage[(size_t)(d0 + dd) * NH + k0 + kk];
        }
        for (int i = threadIdx.x; i < 2048; i += 256) {
            int kk = i >> 6, bb = i & 63;
            sh[kk][bb] = hT[(k0 + kk) * NB + b0 + bb];
        }
        __syncthreads();
        #pragma unroll 8
        for (int kk = 0; kk < 32; kk++) {
            float4 hv = *(const float4*)&sh[kk][bb0];
            #pragma unroll
            for (int di = 0; di < 4; di++) {
                float wv = sWg[dd0 + di][kk];
                acc[di][0] = fmaf(wv, hv.x, acc[di][0]);
                acc[di][1] = fmaf(wv, hv.y, acc[di][1]);
                acc[di][2] = fmaf(wv, hv.z, acc[di][2]);
                acc[di][3] = fmaf(wv, hv.w, acc[di][3]);
            }
        }
    }

    #pragma unroll
    for (int di = 0; di < 4; di++) {
        int d = d0 + dd0 + di;
        float base = bage[d];
        #pragma unroll
        for (int bi = 0; bi < 4; bi++) {
            int b = b0 + bb0 + bi;
            float v = acc[di][bi] + base;
            if (d < NI * NH) {
                int hr = d >> 4, ii = d & 15;
                g_Bm[(size_t)b * (NI * NH) + ii * NH + hr] = v + Wih[d];
            } else if (d < NI * NH + NH * NH) {
                int dd = d - NI * NH;
                int hr = dd >> 8, kk = dd & 255;
                g_A[(size_t)b * (NH * NH) + kk * NH + hr] = v + Whh[dd];
            } else {
                int j = d - (NI * NH + NH * NH);
                g_C[b * NH + j] = v + bih[j] + bhh[j];
            }
        }
    }
}

// -------------------- Bu = einsum('bhi,bti->bth') -----------------------
__global__ void bu_kernel(const float* __restrict__ u)
{
    __shared__ float sBm[NI][NH];
    __shared__ float su2[32][NI];

    const int b = blockIdx.x;
    const int tblk = blockIdx.y * 32;
    const int h = threadIdx.x;

    for (int i = threadIdx.x; i < NI * NH; i += 256) {
        sBm[i >> 8][i & 255] = g_Bm[(size_t)b * (NI * NH) + i];
    }
    for (int i = threadIdx.x; i < 32 * NI; i += 256) {
        int tt = i >> 4, ii = i & 15;
        int t = tblk + tt;
        su2[tt][ii] = (t < NT) ? u[(size_t)b * (NT * NIX) + t * NIX + ii] : 0.f;
    }
    __syncthreads();

    for (int tt = 0; tt < 32; tt++) {
        int t = tblk + tt;
        if (t >= NT) break;
        float acc = 0.f;
        #pragma unroll
        for (int ii = 0; ii < NI; ii++)
            acc = fmaf(sBm[ii][h], su2[tt][ii], acc);
        g_Bu[((size_t)b * NT + t) * NH + h] = acc;
    }
}

// -------------------- fixed point + Euler + output ----------------------
#define SMEM_K 128
#define REG_K  128

__device__ __forceinline__ float dotA(const float* __restrict__ sA,
                                      const float* __restrict__ Areg,
                                      const float* __restrict__ sx,
                                      int h)
{
    float acc = 0.f;
    const float4* sx4 = (const float4*)sx;
    #pragma unroll 4
    for (int k4 = 0; k4 < SMEM_K / 4; k4++) {
        float4 xv = sx4[k4];
        int kb = k4 * 4;
        acc = fmaf(sA[(kb + 0) * NH + h], xv.x, acc);
        acc = fmaf(sA[(kb + 1) * NH + h], xv.y, acc);
        acc = fmaf(sA[(kb + 2) * NH + h], xv.z, acc);
        acc = fmaf(sA[(kb + 3) * NH + h], xv.w, acc);
    }
    #pragma unroll
    for (int k4 = 0; k4 < REG_K / 4; k4++) {
        float4 xv = sx4[SMEM_K / 4 + k4];
        acc = fmaf(Areg[k4 * 4 + 0], xv.x, acc);
        acc = fmaf(Areg[k4 * 4 + 1], xv.y, acc);
        acc = fmaf(Areg[k4 * 4 + 2], xv.z, acc);
        acc = fmaf(Areg[k4 * 4 + 3], xv.w, acc);
    }
    return acc;
}

__global__ void __launch_bounds__(256, 1)
fpeuler_kernel(const float* __restrict__ tau,
               const float* __restrict__ Wout,  // [8,256]
               const float* __restrict__ bout,
               float* __restrict__ out)         // [b][t][8]
{
    extern __shared__ float sA[];                 // [SMEM_K][256]
    __shared__ __align__(16) float sx[NH];

    const int b = blockIdx.x;
    const int h = threadIdx.x;
    const float* __restrict__ Ab = g_A + (size_t)b * (NH * NH);

    for (int idx = h; idx < SMEM_K * NH; idx += 256)
        sA[idx] = Ab[idx];
    float Areg[REG_K];
    #pragma unroll
    for (int r = 0; r < REG_K; r++)
        Areg[r] = Ab[(SMEM_K + r) * NH + h];

    const float Cv  = g_C[b * NH + h];
    const float et  = expf(tau[h]);
    const float* __restrict__ BuB = g_Bu + (size_t)b * NT * NH + h;
    const float bu0 = BuB[0];

    const int w = h >> 5, l = h & 31;
    float wo[8];
    #pragma unroll
    for (int j = 0; j < 8; j++) wo[j] = Wout[w * NH + l * 8 + j];
    const float bo = bout[w];

    float myx = 0.f;
    sx[h] = 0.f;
    __syncthreads();

    for (int it = 0; it < FPIT; it++) {
        float acc = dotA(sA, Areg, sx, h);
        float xn = et * tanhf(acc + bu0 + Cv);
        __syncthreads();
        sx[h] = xn;
        myx = xn;
        __syncthreads();
    }

    {
        const float4* p = (const float4*)(sx + l * 8);
        float4 v0 = p[0], v1 = p[1];
        float a = wo[0] * v0.x;
        a = fmaf(wo[1], v0.y, a); a = fmaf(wo[2], v0.z, a); a = fmaf(wo[3], v0.w, a);
        a = fmaf(wo[4], v1.x, a); a = fmaf(wo[5], v1.y, a);
        a = fmaf(wo[6], v1.z, a); a = fmaf(wo[7], v1.w, a);
        #pragma unroll
        for (int off = 16; off; off >>= 1) a += __shfl_xor_sync(0xffffffffu, a, off);
        if (l == 0) out[((size_t)b * NT + 0) * NO + w] = a + bo;
    }

    float bu = bu0;
    for (int k = 0; k < NT - 1; k++) {
        float bu_nx = (k < NT - 2) ? BuB[(size_t)(k + 1) * NH] : 0.f;
        float acc = dotA(sA, Areg, sx, h);
        float xn = myx + tanhf(acc + bu + Cv) - myx / et;
        __syncthreads();
        sx[h] = xn;
        myx = xn;
        __syncthreads();

        const float4* p = (const float4*)(sx + l * 8);
        float4 v0 = p[0], v1 = p[1];
        float a = wo[0] * v0.x;
        a = fmaf(wo[1], v0.y, a); a = fmaf(wo[2], v0.z, a); a = fmaf(wo[3], v0.w, a);
        a = fmaf(wo[4], v1.x, a); a = fmaf(wo[5], v1.y, a);
        a = fmaf(wo[6], v1.z, a); a = fmaf(wo[7], v1.w, a);
        #pragma unroll
        for (int off = 16; off; off >>= 1) a += __shfl_xor_sync(0xffffffffu, a, off);
        if (l == 0) out[((size_t)b * NT + (k + 1)) * NO + w] = a + bo;

        bu = bu_nx;
    }
}

// -------------------- launch --------------------------------------------
extern "C" void kernel_launch(void* const* d_in, const int* in_sizes, int n_in,
                              void* d_out, int out_size)
{
    const float* u    = (const float*)d_in[0];
    const float* gWih = (const float*)d_in[1];
    const float* gWhh = (const float*)d_in[2];
    const float* gbih = (const float*)d_in[3];
    const float* gbhh = (const float*)d_in[4];
    const float* Wage = (const float*)d_in[5];
    const float* bage = (const float*)d_in[6];
    const float* Wih  = (const float*)d_in[7];
    const float* Whh  = (const float*)d_in[8];
    const float* bih  = (const float*)d_in[9];
    const float* bhh  = (const float*)d_in[10];
    const float* tau  = (const float*)d_in[11];
    const float* Wout = (const float*)d_in[12];
    const float* bout = (const float*)d_in[13];
    float* out = (float*)d_out;

    // persistent GRU scan: one kernel, 16 clusters x 8 CTAs
    const int GRU_SMEM = (24576 + 1632 + BG * SHS + BG * 20) * (int)sizeof(float);
    cudaFuncSetAttribute(gru_scan_kernel,
                         cudaFuncAttributeMaxDynamicSharedMemorySize, GRU_SMEM);
    gru_scan_kernel<<<128, 256, GRU_SMEM>>>(u, gWih, gWhh, gbih, gbhh);

    float* hT = nullptr;
    cudaGetSymbolAddress((void**)&hT, g_hT);

    hyper_kernel<<<dim3(ND / 64, NB / 64), 256>>>(Wage, bage, Wih, Whh, bih, bhh, hT);

    bu_kernel<<<dim3(NB, (NT + 31) / 32), 256>>>(u);

    cudaFuncSetAttribute(fpeuler_kernel,
                         cudaFuncAttributeMaxDynamicSharedMemorySize,
                         SMEM_K * NH * (int)sizeof(float));
    fpeuler_kernel<<<NB, 256, SMEM_K * NH * sizeof(float)>>>(tau, Wout, bout, out);
}

// round 6
// speedup vs baseline: 1.2713x; 1.0009x over previous
#include <cuda_runtime.h>
#include <cuda_bf16.h>
#include <math.h>

// Problem constants
#define NB    256   // BATCH
#define NH    256   // NHIDDEN == NHAGE
#define NI    16    // NINPUT
#define NIX   17    // NINPUT + 1
#define NT    501   // NSTEP
#define ND    69888 // NI*NH + NH*NH + NH
#define NO    8     // NOUT
#define FPIT  100

// GRU persistent-cluster config
#define CLS   8     // CTAs per cluster
#define BG    16    // batches per cluster
#define HPC   32    // hidden indices per CTA
#define SHS   260   // padded h-row stride (floats)

// -------------------- device scratch --------------------------------------
__device__ float g_hx[2][NB][NH];            // h exchange, double-buffered, [b][k]
__device__ float g_hT[NH][NB];               // final h, [j][b] for hyper kernel
__device__ float g_A [NB * NH * NH];         // A^T per batch: [b][k][h]
__device__ float g_Bm[NB * NI * NH];         // Bm per batch:  [b][i][h]
__device__ float g_C [NB * NH];              // [b][h]
__device__ float g_Bu[(size_t)NB * NT * NH]; // [b][t][h]

// -------------------- f32x2 helpers ----------------------------------------
__device__ __forceinline__ unsigned long long pk2(float lo, float hi) {
    unsigned long long r;
    asm("mov.b64 %0, {%1, %2};" : "=l"(r) : "f"(lo), "f"(hi));
    return r;
}
__device__ __forceinline__ void upk2(unsigned long long v, float& lo, float& hi) {
    asm("mov.b64 {%0, %1}, %2;" : "=f"(lo), "=f"(hi) : "l"(v));
}
#define FMA2(acc, a, b) \
    asm("fma.rn.f32x2 %0, %1, %2, %0;" : "+l"(acc) : "l"(a), "l"(b))

// -------------------- persistent GRU scan ---------------------------------
// grid 128 = 16 clusters x 8 CTAs, 256 threads. Cluster cl owns batches
// [cl*16, cl*16+16). CTA rank owns hidden [rank*32, rank*32+32) for all 3
// gate strips; those 96 Whh rows live in smem (interleaved f32x2 layout) for
// the whole scan. h exchanged through L2 each step.
__global__ void __launch_bounds__(256, 1) __cluster_dims__(CLS, 1, 1)
gru_scan_kernel(const float* __restrict__ u,
                const float* __restrict__ gWih,  // [768,17]
                const float* __restrict__ gWhh,  // [768,256]
                const float* __restrict__ gbih,
                const float* __restrict__ gbhh)
{
    extern __shared__ float sm[];
    float* sW  = sm;             // 3*128*16 ulonglong2: ((s*128+kk2)*16+hp) -> {w(k0,h0),w(k0,h1),w(k1,h0),w(k1,h1)}
    float* sWi = sm + 24576;     // 3*17*16 ull: ((s*17+ii)*16+hp) -> {w(ii,h0),w(ii,h1)}
    float* sh  = sm + 26208;     // [16][SHS] h, [b][k]
    float* su  = sm + 30368;     // [16][20] inputs this step

    const int tid   = threadIdx.x;
    const int rank  = blockIdx.x & (CLS - 1);
    const int cl    = blockIdx.x / CLS;
    const int batch0 = cl * BG;
    const int hb    = rank * HPC;

    const int hp = tid & 15;     // hidden pair 0..15
    const int bb = tid >> 4;     // batch 0..15

    // ---- one-time weight load: Whh rows for this CTA, interleaved ----
    for (int idx = tid; idx < 3 * HPC * NH; idx += 256) {
        int r = idx >> 8, k = idx & 255;
        int s = r >> 5, hh = r & 31;
        float w = gWhh[(size_t)(s * NH + hb + hh) * NH + k];
        int kk2 = k >> 1, kb = k & 1, hpd = hh >> 1, hbit = hh & 1;
        sW[(((s * 128 + kk2) * 16 + hpd) << 2) + (kb << 1) + hbit] = w;
    }
    for (int idx = tid; idx < 3 * HPC * NIX; idx += 256) {
        int r = idx / NIX, ii = idx % NIX;
        int s = r >> 5, hh = r & 31;
        float w = gWih[(s * NH + hb + hh) * NIX + ii];
        sWi[((s * 17 + ii) * 16 + (hh >> 1)) * 2 + (hh & 1)] = w;
    }
    for (int idx = tid; idx < BG * SHS; idx += 256) sh[idx] = 0.f;

    // ---- packed biases for this thread's hidden pair ----
    const int g0 = hb + 2 * hp, g1 = g0 + 1;
    const unsigned long long bR2  = pk2(gbih[0*NH+g0] + gbhh[0*NH+g0],
                                        gbih[0*NH+g1] + gbhh[0*NH+g1]);
    const unsigned long long bZ2  = pk2(gbih[1*NH+g0] + gbhh[1*NH+g0],
                                        gbih[1*NH+g1] + gbhh[1*NH+g1]);
    const unsigned long long bNi2 = pk2(gbih[2*NH+g0], gbih[2*NH+g1]);
    const unsigned long long bNh2 = pk2(gbhh[2*NH+g0], gbhh[2*NH+g1]);

    const ulonglong2* wB = (const ulonglong2*)sW;
    const unsigned long long* wiB = (const unsigned long long*)sWi;
    const float* xrow = sh + bb * SHS;
    const float* srow = su + bb * 20;

    for (int t = 0; t < NT; t++) {
        // inputs for step t
        for (int idx = tid; idx < BG * NIX; idx += 256) {
            int b = idx / NIX, ii = idx % NIX;
            su[b * 20 + ii] = u[(size_t)(batch0 + b) * (NT * NIX) + t * NIX + ii];
        }
        __syncthreads();

        unsigned long long accR = bR2, accZ = bZ2, accNi = bNi2, accNh = bNh2;

        #pragma unroll 2
        for (int kk2 = 0; kk2 < 128; kk2 += 2) {
            float4 xv = *(const float4*)(xrow + 2 * kk2);
            unsigned long long x0 = pk2(xv.x, xv.x);
            unsigned long long x1 = pk2(xv.y, xv.y);
            unsigned long long x2 = pk2(xv.z, xv.z);
            unsigned long long x3 = pk2(xv.w, xv.w);
            ulonglong2 wr0 = wB[(0 * 128 + kk2    ) * 16 + hp];
            ulonglong2 wr1 = wB[(0 * 128 + kk2 + 1) * 16 + hp];
            ulonglong2 wz0 = wB[(1 * 128 + kk2    ) * 16 + hp];
            ulonglong2 wz1 = wB[(1 * 128 + kk2 + 1) * 16 + hp];
            ulonglong2 wn0 = wB[(2 * 128 + kk2    ) * 16 + hp];
            ulonglong2 wn1 = wB[(2 * 128 + kk2 + 1) * 16 + hp];
            FMA2(accR, wr0.x, x0); FMA2(accR, wr0.y, x1);
            FMA2(accR, wr1.x, x2); FMA2(accR, wr1.y, x3);
            FMA2(accZ, wz0.x, x0); FMA2(accZ, wz0.y, x1);
            FMA2(accZ, wz1.x, x2); FMA2(accZ, wz1.y, x3);
            FMA2(accNh, wn0.x, x0); FMA2(accNh, wn0.y, x1);
            FMA2(accNh, wn1.x, x2); FMA2(accNh, wn1.y, x3);
        }

        // input contribution
        #pragma unroll
        for (int ii = 0; ii < NIX; ii++) {
            float xs = srow[ii];
            unsigned long long x2i = pk2(xs, xs);
            FMA2(accR,  wiB[(0 * 17 + ii) * 16 + hp], x2i);
            FMA2(accZ,  wiB[(1 * 17 + ii) * 16 + hp], x2i);
            FMA2(accNi, wiB[(2 * 17 + ii) * 16 + hp], x2i);
        }

        // gate nonlinearity + h update for (g0,g1) x batch bb
        float r0, r1, z0, z1, ni0, ni1, nh0, nh1;
        upk2(accR, r0, r1); upk2(accZ, z0, z1);
        upk2(accNi, ni0, ni1); upk2(accNh, nh0, nh1);
        float ho0 = xrow[g0], ho1 = xrow[g1];
        float rr0 = 1.f / (1.f + expf(-r0)), rr1 = 1.f / (1.f + expf(-r1));
        float zz0 = 1.f / (1.f + expf(-z0)), zz1 = 1.f / (1.f + expf(-z1));
        float n0 = tanhf(ni0 + rr0 * nh0),   n1 = tanhf(ni1 + rr1 * nh1);
        float hn0 = (1.f - zz0) * n0 + zz0 * ho0;
        float hn1 = (1.f - zz1) * n1 + zz1 * ho1;

        const int par = t & 1;
        __stcg((float2*)&g_hx[par][batch0 + bb][g0], make_float2(hn0, hn1));
        if (t == NT - 1) {
            g_hT[g0][batch0 + bb] = hn0;
            g_hT[g1][batch0 + bb] = hn1;
        }
        __threadfence();
        asm volatile("barrier.cluster.arrive.aligned;" ::: "memory");
        asm volatile("barrier.cluster.wait.aligned;"   ::: "memory");

        // reload full h (all 256 hidden for our 16 batches)
        const float* gsrc = &g_hx[par][batch0][0];
        for (int idx = tid; idx < BG * NH; idx += 256) {
            int b = idx >> 8, k = idx & 255;
            sh[b * SHS + k] = __ldcg(gsrc + b * NH + k);
        }
        // next iteration's __syncthreads (after su load) orders sh/su writes
    }
}

// -------------------- hypernetwork GEMM ---------------------------------
__global__ void hyper_kernel(const float* __restrict__ Wage,
                             const float* __restrict__ bage,
                             const float* __restrict__ Wih,   // [256,16]
                             const float* __restrict__ Whh,   // [256,256]
                             const float* __restrict__ bih,
                             const float* __restrict__ bhh,
                             const float* __restrict__ hT)    // [j][b]
{
    __shared__ float sWg[64][33];
    __shared__ float sh[32][64];

    const int d0 = blockIdx.x * 64;
    const int b0 = blockIdx.y * 64;
    const int bb0 = (threadIdx.x & 15) * 4;
    const int dd0 = (threadIdx.x >> 4) * 4;

    float acc[4][4] = {};

    for (int k0 = 0; k0 < NH; k0 += 32) {
        __syncthreads();
        for (int i = threadIdx.x; i < 2048; i += 256) {
            int dd = i >> 5, kk = i & 31;
            sWg[dd][kk] = Wage[(size_t)(d0 + dd) * NH + k0 + kk];
        }
        for (int i = threadIdx.x; i < 2048; i += 256) {
            int kk = i >> 6, bb = i & 63;
            sh[kk][bb] = hT[(k0 + kk) * NB + b0 + bb];
        }
        __syncthreads();
        #pragma unroll 8
        for (int kk = 0; kk < 32; kk++) {
            float4 hv = *(const float4*)&sh[kk][bb0];
            #pragma unroll
            for (int di = 0; di < 4; di++) {
                float wv = sWg[dd0 + di][kk];
                acc[di][0] = fmaf(wv, hv.x, acc[di][0]);
                acc[di][1] = fmaf(wv, hv.y, acc[di][1]);
                acc[di][2] = fmaf(wv, hv.z, acc[di][2]);
                acc[di][3] = fmaf(wv, hv.w, acc[di][3]);
            }
        }
    }

    #pragma unroll
    for (int di = 0; di < 4; di++) {
        int d = d0 + dd0 + di;
        float base = bage[d];
        #pragma unroll
        for (int bi = 0; bi < 4; bi++) {
            int b = b0 + bb0 + bi;
            float v = acc[di][bi] + base;
            if (d < NI * NH) {
                int hr = d >> 4, ii = d & 15;
                g_Bm[(size_t)b * (NI * NH) + ii * NH + hr] = v + Wih[d];
            } else if (d < NI * NH + NH * NH) {
                int dd = d - NI * NH;
                int hr = dd >> 8, kk = dd & 255;
                g_A[(size_t)b * (NH * NH) + kk * NH + hr] = v + Whh[dd];
            } else {
                int j = d - (NI * NH + NH * NH);
                g_C[b * NH + j] = v + bih[j] + bhh[j];
            }
        }
    }
}

// -------------------- Bu = einsum('bhi,bti->bth') -----------------------
__global__ void bu_kernel(const float* __restrict__ u)
{
    __shared__ float sBm[NI][NH];
    __shared__ float su2[32][NI];

    const int b = blockIdx.x;
    const int tblk = blockIdx.y * 32;
    const int h = threadIdx.x;

    for (int i = threadIdx.x; i < NI * NH; i += 256) {
        sBm[i >> 8][i & 255] = g_Bm[(size_t)b * (NI * NH) + i];
    }
    for (int i = threadIdx.x; i < 32 * NI; i += 256) {
        int tt = i >> 4, ii = i & 15;
        int t = tblk + tt;
        su2[tt][ii] = (t < NT) ? u[(size_t)b * (NT * NIX) + t * NIX + ii] : 0.f;
    }
    __syncthreads();

    for (int tt = 0; tt < 32; tt++) {
        int t = tblk + tt;
        if (t >= NT) break;
        float acc = 0.f;
        #pragma unroll
        for (int ii = 0; ii < NI; ii++)
            acc = fmaf(sBm[ii][h], su2[tt][ii], acc);
        g_Bu[((size_t)b * NT + t) * NH + h] = acc;
    }
}

// -------------------- fixed point + Euler + output ----------------------
#define SMEM_K 128
#define REG_K  128

__device__ __forceinline__ float dotA(const float* __restrict__ sA,
                                      const float* __restrict__ Areg,
                                      const float* __restrict__ sx,
                                      int h)
{
    float acc = 0.f;
    const float4* sx4 = (const float4*)sx;
    #pragma unroll 4
    for (int k4 = 0; k4 < SMEM_K / 4; k4++) {
        float4 xv = sx4[k4];
        int kb = k4 * 4;
        acc = fmaf(sA[(kb + 0) * NH + h], xv.x, acc);
        acc = fmaf(sA[(kb + 1) * NH + h], xv.y, acc);
        acc = fmaf(sA[(kb + 2) * NH + h], xv.z, acc);
        acc = fmaf(sA[(kb + 3) * NH + h], xv.w, acc);
    }
    #pragma unroll
    for (int k4 = 0; k4 < REG_K / 4; k4++) {
        float4 xv = sx4[SMEM_K / 4 + k4];
        acc = fmaf(Areg[k4 * 4 + 0], xv.x, acc);
        acc = fmaf(Areg[k4 * 4 + 1], xv.y, acc);
        acc = fmaf(Areg[k4 * 4 + 2], xv.z, acc);
        acc = fmaf(Areg[k4 * 4 + 3], xv.w, acc);
    }
    return acc;
}

__global__ void __launch_bounds__(256, 1)
fpeuler_kernel(const float* __restrict__ tau,
               const float* __restrict__ Wout,  // [8,256]
               const float* __restrict__ bout,
               float* __restrict__ out)         // [b][t][8]
{
    extern __shared__ float sA[];                 // [SMEM_K][256]
    __shared__ __align__(16) float sx[NH];

    const int b = blockIdx.x;
    const int h = threadIdx.x;
    const float* __restrict__ Ab = g_A + (size_t)b * (NH * NH);

    for (int idx = h; idx < SMEM_K * NH; idx += 256)
        sA[idx] = Ab[idx];
    float Areg[REG_K];
    #pragma unroll
    for (int r = 0; r < REG_K; r++)
        Areg[r] = Ab[(SMEM_K + r) * NH + h];

    const float Cv  = g_C[b * NH + h];
    const float et  = expf(tau[h]);
    const float* __restrict__ BuB = g_Bu + (size_t)b * NT * NH + h;
    const float bu0 = BuB[0];

    const int w = h >> 5, l = h & 31;
    float wo[8];
    #pragma unroll
    for (int j = 0; j < 8; j++) wo[j] = Wout[w * NH + l * 8 + j];
    const float bo = bout[w];

    float myx = 0.f;
    sx[h] = 0.f;
    __syncthreads();

    for (int it = 0; it < FPIT; it++) {
        float acc = dotA(sA, Areg, sx, h);
        float xn = et * tanhf(acc + bu0 + Cv);
        __syncthreads();
        sx[h] = xn;
        myx = xn;
        __syncthreads();
    }

    {
        const float4* p = (const float4*)(sx + l * 8);
        float4 v0 = p[0], v1 = p[1];
        float a = wo[0] * v0.x;
        a = fmaf(wo[1], v0.y, a); a = fmaf(wo[2], v0.z, a); a = fmaf(wo[3], v0.w, a);
        a = fmaf(wo[4], v1.x, a); a = fmaf(wo[5], v1.y, a);
        a = fmaf(wo[6], v1.z, a); a = fmaf(wo[7], v1.w, a);
        #pragma unroll
        for (int off = 16; off; off >>= 1) a += __shfl_xor_sync(0xffffffffu, a, off);
        if (l == 0) out[((size_t)b * NT + 0) * NO + w] = a + bo;
    }

    float bu = bu0;
    for (int k = 0; k < NT - 1; k++) {
        float bu_nx = (k < NT - 2) ? BuB[(size_t)(k + 1) * NH] : 0.f;
        float acc = dotA(sA, Areg, sx, h);
        float xn = myx + tanhf(acc + bu + Cv) - myx / et;
        __syncthreads();
        sx[h] = xn;
        myx = xn;
        __syncthreads();

        const float4* p = (const float4*)(sx + l * 8);
        float4 v0 = p[0], v1 = p[1];
        float a = wo[0] * v0.x;
        a = fmaf(wo[1], v0.y, a); a = fmaf(wo[2], v0.z, a); a = fmaf(wo[3], v0.w, a);
        a = fmaf(wo[4], v1.x, a); a = fmaf(wo[5], v1.y, a);
        a = fmaf(wo[6], v1.z, a); a = fmaf(wo[7], v1.w, a);
        #pragma unroll
        for (int off = 16; off; off >>= 1) a += __shfl_xor_sync(0xffffffffu, a, off);
        if (l == 0) out[((size_t)b * NT + (k + 1)) * NO + w] = a + bo;

        bu = bu_nx;
    }
}

// -------------------- launch --------------------------------------------
extern "C" void kernel_launch(void* const* d_in, const int* in_sizes, int n_in,
                              void* d_out, int out_size)
{
    const float* u    = (const float*)d_in[0];
    const float* gWih = (const float*)d_in[1];
    const float* gWhh = (const float*)d_in[2];
    const float* gbih = (const float*)d_in[3];
    const float* gbhh = (const float*)d_in[4];
    const float* Wage = (const float*)d_in[5];
    const float* bage = (const float*)d_in[6];
    const float* Wih  = (const float*)d_in[7];
    const float* Whh  = (const float*)d_in[8];
    const float* bih  = (const float*)d_in[9];
    const float* bhh  = (const float*)d_in[10];
    const float* tau  = (const float*)d_in[11];
    const float* Wout = (const float*)d_in[12];
    const float* bout = (const float*)d_in[13];
    float* out = (float*)d_out;

    // persistent GRU scan: one kernel, 16 clusters x 8 CTAs
    const int GRU_SMEM = (24576 + 1632 + BG * SHS + BG * 20) * (int)sizeof(float);
    cudaFuncSetAttribute(gru_scan_kernel,
                         cudaFuncAttributeMaxDynamicSharedMemorySize, GRU_SMEM);
    gru_scan_kernel<<<128, 256, GRU_SMEM>>>(u, gWih, gWhh, gbih, gbhh);

    float* hT = nullptr;
    cudaGetSymbolAddress((void**)&hT, g_hT);

    hyper_kernel<<<dim3(ND / 64, NB / 64), 256>>>(Wage, bage, Wih, Whh, bih, bhh, hT);

    bu_kernel<<<dim3(NB, (NT + 31) / 32), 256>>>(u);

    cudaFuncSetAttribute(fpeuler_kernel,
                         cudaFuncAttributeMaxDynamicSharedMemorySize,
                         SMEM_K * NH * (int)sizeof(float));
    fpeuler_kernel<<<NB, 256, SMEM_K * NH * sizeof(float)>>>(tau, Wout, bout, out);
}